// round 11
// baseline (speedup 1.0000x reference)
#include <cuda_runtime.h>

// RoiPooling: crop_and_resize(img[0], 2048 boxes, crop=7) over 512 channels.
// CTA = box, 128 threads = 512 channels as float4.
// Raw 2-row patch register cache (pT/pB): rows are nondecreasing, step <= 1,
// so each advance is pT <- pB + one fresh 6-load row (~36 LDG.128/box).
// Select-free 3-tap window weights (Wa/Wb/Wc) live in SHARED memory, read
// through a volatile pointer so they cost 0 persistent registers per thread
// (they are CTA-uniform; holding them in regs caused spills at the 128 cap).

#define IMG_H 28
#define IMG_W 28
#define C4    128          // 512 channels / 4
#define POOLN 7
#define NBOX  2048
#define ROWSTRIDE (IMG_W * C4)   // float4 elems per image row

#define LOADROW(rowc, dst) do {                                               \
    const float4* rp_ = base_img + (rowc) * ROWSTRIDE;                        \
    _Pragma("unroll")                                                         \
    for (int k_ = 0; k_ < 6; k_++) (dst)[k_] = __ldg(rp_ + colofs[k_]);       \
} while (0)

__global__ __launch_bounds__(128, 4) void roi_pool_kernel(
    const float4* __restrict__ img4,   // img[0] as float4: (28*28, 128)
    const float*  __restrict__ rois,
    float4* __restrict__ out4)
{
    // floor(j * 27*4/(28*6)) for j=0..6; j*sx stays >=0.07 from any integer,
    // far beyond f32 rounding wiggle, so ax[j]-ax[0] ∈ {BASE, BASE+1}.
    const int BASE_X[POOLN] = {0, 0, 1, 1, 2, 3, 3};

    __shared__ float sW[3 * POOLN];        // Wa[7] | Wb[7] | Wc[7]

    const int box = blockIdx.x;
    const int tid = threadIdx.x;           // channel-quad 0..127

    const float x1 = rois[box * 5 + 3];
    const float y1 = rois[box * 5 + 4];
    const float win = (float)(4.0 / 28.0);
    // Match JAX numerics: ((x1+win)-x1)*27/6 in f32
    const float sx = (((x1 + win) - x1) * 27.0f) / 6.0f;
    const float sy = (((y1 + win) - y1) * 27.0f) / 6.0f;
    const float fx = x1 * 27.0f;
    const float fy = y1 * 27.0f;

    const int x_lo = (int)floorf(fx);      // rois >= 0 so fx >= 0

    // ---- per-box x setup: select-free 3-tap weights -> shared ----
    if (tid == 0) {
#pragma unroll
        for (int j = 0; j < POOLN; j++) {
            float xs = fx + (float)j * sx;
            float xf = floorf(xs);
            float l = xs - xf;
            int ax = (int)xf;
            bool c = (ax - x_lo) > BASE_X[j];   // sample one column right
            float m = (xs <= 27.0f) ? 1.0f : 0.0f;
            float u0 = m * (1.0f - l);
            float u1 = m * l;
            sW[j]             = c ? 0.0f : u0;
            sW[POOLN + j]     = c ? u0   : u1;
            sW[2 * POOLN + j] = c ? u1   : 0.0f;
        }
    }

    int colofs[6];
#pragma unroll
    for (int k = 0; k < 6; k++)
        colofs[k] = min(x_lo + k, IMG_W - 1) * C4;

    const float4* base_img = img4 + tid;
    float4* outp = out4 + (size_t)box * (POOLN * POOLN) * C4 + tid;

    __syncthreads();
    volatile const float* vW = sW;         // defeat register promotion

    // ---- raw 2-row patch cache ----
    float4 pT[6], pB[6];
    int ct;
    {
        int ya0 = (int)floorf(fy);
        ct = min(ya0, IMG_H - 1);
        int cb = min(ya0 + 1, IMG_H - 1);
        LOADROW(ct, pT);
        if (cb != ct) {
            LOADROW(cb, pB);
        } else {
#pragma unroll
            for (int k = 0; k < 6; k++) pB[k] = pT[k];
        }
    }

#pragma unroll
    for (int i = 0; i < POOLN; i++) {
        float ys = fy + (float)i * sy;
        float yf = floorf(ys);
        float ly = ys - yf;
        int ya = (int)yf;
        int t = min(ya, IMG_H - 1);
        int b = min(ya + 1, IMG_H - 1);
        float my = (ys <= 27.0f) ? 1.0f : 0.0f;
        float wA = (1.0f - ly) * my;
        float wB = ly * my;

        if (i > 0 && t != ct) {
            // advance by exactly one image row: new top == old bottom
#pragma unroll
            for (int k = 0; k < 6; k++) pT[k] = pB[k];
            if (b != t) {
                LOADROW(b, pB);
            } else {
#pragma unroll
                for (int k = 0; k < 6; k++) pB[k] = pT[k];
            }
            ct = t;
        }

        // y-blend the patch row (transient)
        float4 ry[6];
#pragma unroll
        for (int k = 0; k < 6; k++) {
            ry[k].x = pT[k].x * wA + pB[k].x * wB;
            ry[k].y = pT[k].y * wA + pB[k].y * wB;
            ry[k].z = pT[k].z * wA + pB[k].z * wB;
            ry[k].w = pT[k].w * wA + pB[k].w * wB;
        }

        // 7 select-free 3-tap outputs; weights streamed from shared
#pragma unroll
        for (int j = 0; j < POOLN; j++) {
            const int bx = BASE_X[j];
            float a  = vW[j];
            float bb = vW[POOLN + j];
            float cc = vW[2 * POOLN + j];
            float4 v;
            v.x = ry[bx].x * a + ry[bx + 1].x * bb + ry[bx + 2].x * cc;
            v.y = ry[bx].y * a + ry[bx + 1].y * bb + ry[bx + 2].y * cc;
            v.z = ry[bx].z * a + ry[bx + 1].z * bb + ry[bx + 2].z * cc;
            v.w = ry[bx].w * a + ry[bx + 1].w * bb + ry[bx + 2].w * cc;
            __stcs(outp + (i * POOLN + j) * C4, v);
        }
    }
}

extern "C" void kernel_launch(void* const* d_in, const int* in_sizes, int n_in,
                              void* d_out, int out_size) {
    const float* img  = (const float*)d_in[0];
    const float* rois = (const float*)d_in[1];
    float* out = (float*)d_out;
    (void)in_sizes; (void)n_in; (void)out_size;
    roi_pool_kernel<<<NBOX, 128>>>((const float4*)img, rois, (float4*)out);
}

// round 13
// speedup vs baseline: 1.0073x; 1.0073x over previous
#include <cuda_runtime.h>

// RoiPooling: crop_and_resize(img[0], 2048 boxes, crop=7) over 512 channels.
// CTA = box, 128 threads = 512 channels as float4.
// Raw 2-row patch register cache (pT/pB, rows advance by <=1 per output row).
// Outputs are FUSED 6-tap FMAs directly on the raw patch: the y-blend is
// folded into per-(i,j) scalar weight products, eliminating the ry[6]
// transient (24 regs). 3-tap x-window weights live in smem (volatile -> no
// register promotion). Fits 5 CTAs/SM for 20 warps of latency cover.

#define IMG_H 28
#define IMG_W 28
#define C4    128          // 512 channels / 4
#define POOLN 7
#define NBOX  2048
#define ROWSTRIDE (IMG_W * C4)   // float4 elems per image row

#define LOADROW(rowc, dst) do {                                               \
    const float4* rp_ = base_img + (rowc) * ROWSTRIDE;                        \
    _Pragma("unroll")                                                         \
    for (int k_ = 0; k_ < 6; k_++) (dst)[k_] = __ldg(rp_ + colofs[k_]);       \
} while (0)

__global__ __launch_bounds__(128, 5) void roi_pool_kernel(
    const float4* __restrict__ img4,   // img[0] as float4: (28*28, 128)
    const float*  __restrict__ rois,
    float4* __restrict__ out4)
{
    // floor(j * 27*4/(28*6)) for j=0..6; j*sx stays >=0.07 from any integer,
    // far beyond f32 rounding wiggle, so ax[j]-ax[0] ∈ {BASE, BASE+1}.
    const int BASE_X[POOLN] = {0, 0, 1, 1, 2, 3, 3};

    __shared__ float sW[3 * POOLN];        // Wa[7] | Wb[7] | Wc[7]

    const int box = blockIdx.x;
    const int tid = threadIdx.x;           // channel-quad 0..127

    const float x1 = rois[box * 5 + 3];
    const float y1 = rois[box * 5 + 4];
    const float win = (float)(4.0 / 28.0);
    // Match JAX numerics: ((x1+win)-x1)*27/6 in f32
    const float sx = (((x1 + win) - x1) * 27.0f) / 6.0f;
    const float sy = (((y1 + win) - y1) * 27.0f) / 6.0f;
    const float fx = x1 * 27.0f;
    const float fy = y1 * 27.0f;

    const int x_lo = (int)floorf(fx);      // rois >= 0 so fx >= 0

    // ---- per-box x setup: select-free 3-tap weights -> shared ----
    if (tid == 0) {
#pragma unroll
        for (int j = 0; j < POOLN; j++) {
            float xs = fx + (float)j * sx;
            float xf = floorf(xs);
            float l = xs - xf;
            int ax = (int)xf;
            bool c = (ax - x_lo) > BASE_X[j];   // sample one column right
            float m = (xs <= 27.0f) ? 1.0f : 0.0f;
            float u0 = m * (1.0f - l);
            float u1 = m * l;
            sW[j]             = c ? 0.0f : u0;
            sW[POOLN + j]     = c ? u0   : u1;
            sW[2 * POOLN + j] = c ? u1   : 0.0f;
        }
    }

    int colofs[6];
#pragma unroll
    for (int k = 0; k < 6; k++)
        colofs[k] = min(x_lo + k, IMG_W - 1) * C4;

    const float4* base_img = img4 + tid;
    float4* outp = out4 + (size_t)box * (POOLN * POOLN) * C4 + tid;

    __syncthreads();
    volatile const float* vW = sW;         // defeat register promotion

    // ---- raw 2-row patch cache ----
    float4 pT[6], pB[6];
    int ct;
    {
        int ya0 = (int)floorf(fy);
        ct = min(ya0, IMG_H - 1);
        int cb = min(ya0 + 1, IMG_H - 1);
        LOADROW(ct, pT);
        if (cb != ct) {
            LOADROW(cb, pB);
        } else {
#pragma unroll
            for (int k = 0; k < 6; k++) pB[k] = pT[k];
        }
    }

#pragma unroll
    for (int i = 0; i < POOLN; i++) {
        float ys = fy + (float)i * sy;
        float yf = floorf(ys);
        float ly = ys - yf;
        int ya = (int)yf;
        int t = min(ya, IMG_H - 1);
        int b = min(ya + 1, IMG_H - 1);
        float my = (ys <= 27.0f) ? 1.0f : 0.0f;
        float wA = (1.0f - ly) * my;
        float wB = ly * my;

        if (i > 0 && t != ct) {
            // advance by exactly one image row: new top == old bottom
#pragma unroll
            for (int k = 0; k < 6; k++) pT[k] = pB[k];
            if (b != t) {
                LOADROW(b, pB);
            } else {
#pragma unroll
                for (int k = 0; k < 6; k++) pB[k] = pT[k];
            }
            ct = t;
        }

        // 7 fused 6-tap outputs directly on the raw patch (no ry transient)
#pragma unroll
        for (int j = 0; j < POOLN; j++) {
            const int bx = BASE_X[j];
            float a  = vW[j];
            float bb = vW[POOLN + j];
            float cc = vW[2 * POOLN + j];
            float ta = wA * a,  ba = wB * a;
            float tb = wA * bb, bbb = wB * bb;
            float tc = wA * cc, bc = wB * cc;
            float4 v;
            v.x = pT[bx].x * ta + pB[bx].x * ba
                + pT[bx+1].x * tb + pB[bx+1].x * bbb
                + pT[bx+2].x * tc + pB[bx+2].x * bc;
            v.y = pT[bx].y * ta + pB[bx].y * ba
                + pT[bx+1].y * tb + pB[bx+1].y * bbb
                + pT[bx+2].y * tc + pB[bx+2].y * bc;
            v.z = pT[bx].z * ta + pB[bx].z * ba
                + pT[bx+1].z * tb + pB[bx+1].z * bbb
                + pT[bx+2].z * tc + pB[bx+2].z * bc;
            v.w = pT[bx].w * ta + pB[bx].w * ba
                + pT[bx+1].w * tb + pB[bx+1].w * bbb
                + pT[bx+2].w * tc + pB[bx+2].w * bc;
            __stcs(outp + (i * POOLN + j) * C4, v);
        }
    }
}

extern "C" void kernel_launch(void* const* d_in, const int* in_sizes, int n_in,
                              void* d_out, int out_size) {
    const float* img  = (const float*)d_in[0];
    const float* rois = (const float*)d_in[1];
    float* out = (float*)d_out;
    (void)in_sizes; (void)n_in; (void)out_size;
    roi_pool_kernel<<<NBOX, 128>>>((const float4*)img, rois, (float4*)out);
}